// round 9
// baseline (speedup 1.0000x reference)
#include <cuda_runtime.h>
#include <cuda_fp16.h>
#include <math.h>

typedef unsigned int       u32;
typedef unsigned long long u64;

// ---------------------------------------------------------------------------
// Problem constants
// ---------------------------------------------------------------------------
#define BB 64
#define FF 128
#define SS 2048
#define FS (FF * SS)          // 262144
#define MROWS (BB * FF)       // 8192
#define UU ((size_t)MROWS * 256)   // one (8192 x 256) fp32 plane

// ---------------------------------------------------------------------------
// Baseline-PTX helpers (cp.async + ldmatrix + mma.sync)
// ---------------------------------------------------------------------------
__device__ __forceinline__ u32 smem_to_u32(const void* p) {
    u32 a;
    asm("{ .reg .u64 t; cvta.to.shared.u64 t, %1; cvt.u32.u64 %0, t; }" : "=r"(a) : "l"(p));
    return a;
}
__device__ __forceinline__ void cp_async16(u32 dst, const void* src) {
    asm volatile("cp.async.cg.shared.global [%0], [%1], 16;" :: "r"(dst), "l"(src) : "memory");
}
#define CP_COMMIT() asm volatile("cp.async.commit_group;" ::: "memory")
#define CP_WAIT(n)  asm volatile("cp.async.wait_group %0;" :: "n"(n) : "memory")

__device__ __forceinline__ void ldsm_x4(u32* r, u32 addr) {
    asm volatile("ldmatrix.sync.aligned.m8n8.x4.shared.b16 {%0,%1,%2,%3}, [%4];"
                 : "=r"(r[0]), "=r"(r[1]), "=r"(r[2]), "=r"(r[3]) : "r"(addr));
}
__device__ __forceinline__ void ldsm_x2(u32* r, u32 addr) {
    asm volatile("ldmatrix.sync.aligned.m8n8.x2.shared.b16 {%0,%1}, [%2];"
                 : "=r"(r[0]), "=r"(r[1]) : "r"(addr));
}
__device__ __forceinline__ void mma_f16(float* c, const u32* a, const u32* b) {
    asm volatile("mma.sync.aligned.m16n8k16.row.col.f32.f16.f16.f32 "
                 "{%0,%1,%2,%3}, {%4,%5,%6,%7}, {%8,%9}, {%0,%1,%2,%3};"
                 : "+f"(c[0]), "+f"(c[1]), "+f"(c[2]), "+f"(c[3])
                 : "r"(a[0]), "r"(a[1]), "r"(a[2]), "r"(a[3]), "r"(b[0]), "r"(b[1]));
}
#define SWZ(b) ((b) ^ (((b) >> 3) & 0x70))

// ---------------------------------------------------------------------------
// Static scratch arenas
// ---------------------------------------------------------------------------
#define OFF_MU     ((size_t)0)
#define OFF_RSTD   (OFF_MU + FS)
#define OFF_AVG0   (OFF_RSTD + FS)
#define OFF_MX0    (OFF_AVG0 + UU)
#define OFF_AVG1   (OFF_MX0 + UU)
#define OFF_MX1    (OFF_AVG1 + 2 * UU)
#define OFF_AVG2   (OFF_MX1 + 2 * UU)
#define OFF_MX2    (OFF_AVG2 + 4 * UU)
#define OFF_MIXF1  (OFF_MX2 + 4 * UU)
#define OFF_MIXF2  (OFF_MIXF1 + 2 * UU)
#define OFF_STATS  (OFF_MIXF2 + 4 * UU)
#define OFF_W      (OFF_STATS + (size_t)3 * 64 * 384)
#define SCRATCH_TOTAL (OFF_W + 3 * 64)
__device__ float g_scratch[SCRATCH_TOTAL];

// fp16 arenas: activations use hi+lo; weights use hi only
#define BO_MIX0  ((size_t)0)
#define BO_S1    (BO_MIX0 + UU)
#define BO_S2    (BO_S1 + 2 * UU)
#define BO_H0    (BO_S2 + 4 * UU)
#define BO_H1    (BO_H0 + UU)
#define BO_H2    (BO_H1 + 2 * UU)
#define BO_WT    (BO_H2 + 4 * UU)
#define BO_WT0A  (BO_WT)
#define BO_WT0B  (BO_WT0A + 256 * 256)
#define BO_WT1A  (BO_WT0B + 512 * 256)
#define BO_WT1B  (BO_WT1A + 512 * 512)
#define BO_WT2A  (BO_WT1B + 1024 * 512)
#define BO_WT2B  (BO_WT2A + 1024 * 1024)
#define BF_TOTAL (BO_WT2B + (size_t)2048 * 1024)
__device__ __half g_hi[BF_TOTAL];
__device__ __half g_lo[BF_TOTAL];      // lo plane used for activations only

__device__ __forceinline__ void split_f16(float v, __half& h, __half& l) {
    h = __float2half(v);
    l = __float2half(v - __half2float(h));
}
__device__ __forceinline__ float gelu_exact(float v) {
    return 0.5f * v * (1.0f + erff(v * 0.70710678118654752f));
}

// ---------------------------------------------------------------------------
// 1) BatchNorm statistics
// ---------------------------------------------------------------------------
__global__ void bn_stats_kernel(const float* __restrict__ x,
                                float* __restrict__ mu, float* __restrict__ rstd)
{
    int j = blockIdx.x * blockDim.x + threadIdx.x;
    float s = 0.f, ss = 0.f;
#pragma unroll 8
    for (int b = 0; b < BB; b++) {
        float v = x[(size_t)b * FS + j];
        s += v; ss += v * v;
    }
    float m   = s * (1.f / BB);
    float var = ss * (1.f / BB) - m * m;
    mu[j]   = m;
    rstd[j] = rsqrtf(var + 1e-5f);
}

// ---------------------------------------------------------------------------
// 2) Fused BN apply + multi-scale pooling + pfs statistics.
// ---------------------------------------------------------------------------
__global__ __launch_bounds__(256)
void bn_pool_stats_kernel(const float* __restrict__ x,
                          const float* __restrict__ gamma,
                          const float* __restrict__ beta,
                          const float* __restrict__ mu,
                          const float* __restrict__ rstd,
                          float* __restrict__ xn,
                          float* __restrict__ avg0, float* __restrict__ mx0,
                          float* __restrict__ avg1, float* __restrict__ mx1,
                          float* __restrict__ avg2, float* __restrict__ mx2,
                          float* __restrict__ stats)
{
    const int bf = blockIdx.x;
    const int b  = bf >> 7;
    const int f  = bf & (FF - 1);
    const int t  = threadIdx.x;
    const size_t base = ((size_t)bf << 11) + (t << 3);
    const int j0 = (f << 11) + (t << 3);

    float4 xa = *(const float4*)(x + base);
    float4 xb = *(const float4*)(x + base + 4);
    float4 ma = *(const float4*)(mu + j0);
    float4 mb = *(const float4*)(mu + j0 + 4);
    float4 ra = *(const float4*)(rstd + j0);
    float4 rb = *(const float4*)(rstd + j0 + 4);
    float4 ga = *(const float4*)(gamma + j0);
    float4 gb = *(const float4*)(gamma + j0 + 4);
    float4 ba = *(const float4*)(beta + j0);
    float4 bb = *(const float4*)(beta + j0 + 4);

    float v[8];
    v[0] = (xa.x - ma.x) * ra.x * ga.x + ba.x;
    v[1] = (xa.y - ma.y) * ra.y * ga.y + ba.y;
    v[2] = (xa.z - ma.z) * ra.z * ga.z + ba.z;
    v[3] = (xa.w - ma.w) * ra.w * ga.w + ba.w;
    v[4] = (xb.x - mb.x) * rb.x * gb.x + bb.x;
    v[5] = (xb.y - mb.y) * rb.y * gb.y + bb.y;
    v[6] = (xb.z - mb.z) * rb.z * gb.z + bb.z;
    v[7] = (xb.w - mb.w) * rb.w * gb.w + bb.w;

    *(float4*)(xn + base)     = make_float4(v[0], v[1], v[2], v[3]);
    *(float4*)(xn + base + 4) = make_float4(v[4], v[5], v[6], v[7]);

    float a2[4], m2[4];
#pragma unroll
    for (int i = 0; i < 4; i++) {
        a2[i] = (v[2 * i] + v[2 * i + 1]) * 0.5f;
        m2[i] = fmaxf(v[2 * i], v[2 * i + 1]);
    }
    size_t b2 = ((size_t)bf << 10) + (t << 2);
#pragma unroll
    for (int i = 0; i < 4; i++) { avg2[b2 + i] = a2[i]; mx2[b2 + i] = m2[i]; }

    float a1[2], m1[2];
    a1[0] = (a2[0] + a2[1]) * 0.5f;  m1[0] = fmaxf(m2[0], m2[1]);
    a1[1] = (a2[2] + a2[3]) * 0.5f;  m1[1] = fmaxf(m2[2], m2[3]);
    size_t b1 = ((size_t)bf << 9) + (t << 1);
    avg1[b1] = a1[0]; mx1[b1] = m1[0];
    avg1[b1 + 1] = a1[1]; mx1[b1 + 1] = m1[1];

    float a0 = (a1[0] + a1[1]) * 0.5f;
    float m0 = fmaxf(m1[0], m1[1]);
    size_t b0 = ((size_t)bf << 8) + t;
    avg0[b0] = a0; mx0[b0] = m0;

    float s[3] = {0.f, 0.f, 0.f}, q[3] = {0.f, 0.f, 0.f}, mm[3] = {-1e30f, -1e30f, -1e30f};
    {
        float p = 0.5f * (a0 + m0);
        s[0] = p; q[0] = p * p; mm[0] = p;
    }
#pragma unroll
    for (int i = 0; i < 2; i++) {
        float p = 0.5f * (a1[i] + m1[i]);
        s[1] += p; q[1] += p * p; mm[1] = fmaxf(mm[1], p);
    }
#pragma unroll
    for (int i = 0; i < 4; i++) {
        float p = 0.5f * (a2[i] + m2[i]);
        s[2] += p; q[2] += p * p; mm[2] = fmaxf(mm[2], p);
    }

    const int lane = t & 31, warp = t >> 5;
#pragma unroll
    for (int off = 16; off > 0; off >>= 1) {
#pragma unroll
        for (int k = 0; k < 3; k++) {
            s[k]  += __shfl_down_sync(0xFFFFFFFFu, s[k], off);
            q[k]  += __shfl_down_sync(0xFFFFFFFFu, q[k], off);
            mm[k]  = fmaxf(mm[k], __shfl_down_sync(0xFFFFFFFFu, mm[k], off));
        }
    }
    __shared__ float red[8][9];
    if (lane == 0) {
#pragma unroll
        for (int k = 0; k < 3; k++) {
            red[warp][k] = s[k]; red[warp][3 + k] = q[k]; red[warp][6 + k] = mm[k];
        }
    }
    __syncthreads();
    if (t == 0) {
        const int Lsc[3] = {256, 512, 1024};
#pragma unroll
        for (int k = 0; k < 3; k++) {
            float S = 0.f, Q = 0.f, M = -1e30f;
#pragma unroll
            for (int w = 0; w < 8; w++) {
                S += red[w][k]; Q += red[w][3 + k]; M = fmaxf(M, red[w][6 + k]);
            }
            float L = (float)Lsc[k];
            float mean = S / L;
            float var  = (Q - S * mean) / (L - 1.f);
            float* st = stats + (size_t)k * 64 * 384 + b * 384;
            st[f]       = mean;
            st[128 + f] = sqrtf(fmaxf(var, 0.f));
            st[256 + f] = M;
        }
    }
}

// ---------------------------------------------------------------------------
// 3) Selector MLPs: grid (64,3), block 256 (4 partial-sum threads per unit)
// ---------------------------------------------------------------------------
struct SelParams {
    const float* w1[3]; const float* b1[3]; const float* w2[3]; const float* b2[3];
};
__global__ __launch_bounds__(256)
void selector_all_kernel(const float* __restrict__ stats, SelParams sp,
                         float* __restrict__ wout)
{
    int s = blockIdx.y, b = blockIdx.x;
    int tid = threadIdx.x;
    int p = tid >> 6, j = tid & 63;
    const float* w1 = sp.w1[s];
    __shared__ float st[384];
    __shared__ float part[4][64];
    __shared__ float sh[64];
    const float* sg = stats + (size_t)s * 64 * 384 + b * 384;
    for (int i = tid; i < 384; i += 256) st[i] = sg[i];
    __syncthreads();
    float acc = 0.f;
#pragma unroll 8
    for (int i = p; i < 384; i += 4) acc += st[i] * __ldg(w1 + i * 64 + j);
    part[p][j] = acc;
    __syncthreads();
    if (tid < 64) {
        float h = part[0][tid] + part[1][tid] + part[2][tid] + part[3][tid] + sp.b1[s][tid];
        sh[tid] = fmaxf(h, 0.f) * sp.w2[s][tid];
    }
    __syncthreads();
    if (tid < 32) {
        float v = sh[tid] + sh[tid + 32];
#pragma unroll
        for (int off = 16; off > 0; off >>= 1)
            v += __shfl_down_sync(0xFFFFFFFFu, v, off);
        if (tid == 0)
            wout[s * 64 + b] = 1.f / (1.f + expf(-(v + sp.b2[s][0])));
    }
}

// ---------------------------------------------------------------------------
// 4) Mix: w*avg+(1-w)*max; optional fp32 out and/or fp16 split out
// ---------------------------------------------------------------------------
__global__ void mix_split_kernel(const float* __restrict__ avg, const float* __restrict__ mx,
                                 const float* __restrict__ wsel,
                                 float* __restrict__ outf,
                                 __half* __restrict__ oh, __half* __restrict__ ol,
                                 int L)
{
    size_t idx = (size_t)blockIdx.x * blockDim.x + threadIdx.x;
    int b = (int)(idx / ((size_t)FF * L));
    float w = wsel[b];
    float v = w * avg[idx] + (1.f - w) * mx[idx];
    if (outf) outf[idx] = v;
    if (oh) {
        __half h, l;
        split_f16(v, h, l);
        oh[idx] = h; ol[idx] = l;
    }
}

// ---------------------------------------------------------------------------
// 5) Weight transpose to [N,K] fp16 (single plane), all 6 in one launch.
// ---------------------------------------------------------------------------
struct WJobs {
    const float* W[6];
    size_t off[6];
    int K[6], N[6];
    int prefix[7];
};
__global__ void wsplit_all_kernel(WJobs jobs, __half* __restrict__ hib)
{
    __shared__ float tile[32][33];
    int bid = blockIdx.x;
    int j = 0;
#pragma unroll
    for (int i = 1; i < 6; i++)
        if (bid >= jobs.prefix[i]) j = i;
    int local = bid - jobs.prefix[j];
    int K = jobs.K[j], N = jobs.N[j];
    const float* W = jobs.W[j];
    __half* Th = hib + jobs.off[j];
    int tiles_x = N >> 5;
    int n0 = (local % tiles_x) << 5, k0 = (local / tiles_x) << 5;
    int tx = threadIdx.x, ty = threadIdx.y;
#pragma unroll
    for (int i = 0; i < 32; i += 8)
        tile[ty + i][tx] = W[(size_t)(k0 + ty + i) * N + n0 + tx];
    __syncthreads();
#pragma unroll
    for (int i = 0; i < 32; i += 8) {
        size_t o = (size_t)(n0 + ty + i) * K + k0 + tx;
        Th[o] = __float2half(tile[tx][ty + i]);
    }
}

// ---------------------------------------------------------------------------
// 6) mma.sync fp16 2-term split GEMM (A=Ah+Al, B single fp16).
//    CTA 128x128, K-chunk 64, 4-stage cp.async pipeline, SW128 swizzle.
//    8 warps 2(M)x4(N), warp tile 64x32.
// ---------------------------------------------------------------------------
#define TILE_BYTES 16384            // 128 rows x 64 fp16
#define STAGE_BYTES (3 * TILE_BYTES)
#define GEMM_SMEM (4 * STAGE_BYTES) // 196608

__global__ __launch_bounds__(256, 1)
void gemm2_mma_kernel(const __half* __restrict__ Ahi, const __half* __restrict__ Alo,
                      const __half* __restrict__ Bw,
                      const float* __restrict__ bias, const float* __restrict__ resid,
                      float* __restrict__ outf,
                      __half* __restrict__ Ohi, __half* __restrict__ Olo,
                      int M, int N, int K, int mode)
{
    extern __shared__ char smem[];
    const u32 sb = smem_to_u32(smem);
    const int tid = threadIdx.x;
    const int wid = tid >> 5, lane = tid & 31;
    const int m0 = blockIdx.y * 128, n0 = blockIdx.x * 128;
    const int wm = (wid & 1) * 64;
    const int wn = (wid >> 1) * 32;

    float acc[4][4][4];
#pragma unroll
    for (int i = 0; i < 4; i++)
#pragma unroll
        for (int j = 0; j < 4; j++)
#pragma unroll
            for (int r = 0; r < 4; r++) acc[i][j][r] = 0.f;

    const int ntile = K >> 6;

#define ISSUE_STAGE(T) do {                                                    \
        const int k0_ = (T) << 6;                                              \
        const u32 stage_ = ((T) & 3) * STAGE_BYTES;                            \
        _Pragma("unroll")                                                      \
        for (int rep = 0; rep < 4; rep++) {                                    \
            int idx = tid + rep * 256;                                         \
            int r = idx >> 3, c = idx & 7;                                     \
            u32 so = SWZ((u32)(r * 128 + c * 16));                             \
            size_t ga = (size_t)(m0 + r) * K + k0_ + c * 8;                    \
            size_t gb = (size_t)(n0 + r) * K + k0_ + c * 8;                    \
            cp_async16(sb + stage_ + 0 * TILE_BYTES + so, Ahi + ga);           \
            cp_async16(sb + stage_ + 1 * TILE_BYTES + so, Alo + ga);           \
            cp_async16(sb + stage_ + 2 * TILE_BYTES + so, Bw + gb);            \
        }                                                                      \
        CP_COMMIT();                                                           \
    } while (0)

    ISSUE_STAGE(0);
    if (ntile > 1) ISSUE_STAGE(1);
    if (ntile > 2) ISSUE_STAGE(2);

    for (int t = 0; t < ntile; t++) {
        if (t + 2 < ntile)      { CP_WAIT(2); }
        else if (t + 1 < ntile) { CP_WAIT(1); }
        else                    { CP_WAIT(0); }
        __syncthreads();
        if (t + 3 < ntile) ISSUE_STAGE(t + 3);   // refills stage (t-1)&3

        const u32 stage = (t & 3) * STAGE_BYTES;
        const u32 sAhi = sb + stage + 0 * TILE_BYTES;
        const u32 sAlo = sb + stage + 1 * TILE_BYTES;
        const u32 sB   = sb + stage + 2 * TILE_BYTES;

#pragma unroll
        for (int ks = 0; ks < 4; ks++) {
            u32 ah[4][4], al[4][4], bw[4][2];
#pragma unroll
            for (int mb = 0; mb < 4; mb++) {
                int row = wm + mb * 16 + (lane & 15);
                u32 so = SWZ((u32)(row * 128 + ks * 32 + (lane >> 4) * 16));
                ldsm_x4(ah[mb], sAhi + so);
                ldsm_x4(al[mb], sAlo + so);
            }
#pragma unroll
            for (int nb = 0; nb < 4; nb++) {
                int row = wn + nb * 8 + (lane & 7);
                u32 so = SWZ((u32)(row * 128 + ks * 32 + ((lane >> 3) & 1) * 16));
                ldsm_x2(bw[nb], sB + so);
            }
#pragma unroll
            for (int mb = 0; mb < 4; mb++)
#pragma unroll
                for (int nb = 0; nb < 4; nb++) {
                    mma_f16(acc[mb][nb], ah[mb], bw[nb]);
                    mma_f16(acc[mb][nb], al[mb], bw[nb]);
                }
        }
    }
#undef ISSUE_STAGE

    const int g   = lane >> 2;
    const int tig = lane & 3;
#pragma unroll
    for (int mb = 0; mb < 4; mb++) {
#pragma unroll
        for (int nb = 0; nb < 4; nb++) {
            int col = n0 + wn + nb * 8 + 2 * tig;
            float bv0 = __ldg(bias + col), bv1 = __ldg(bias + col + 1);
#pragma unroll
            for (int hrow = 0; hrow < 2; hrow++) {
                int row = m0 + wm + mb * 16 + g + hrow * 8;
                size_t ob = (size_t)row * N + col;
                float v0 = acc[mb][nb][hrow * 2 + 0] + bv0;
                float v1 = acc[mb][nb][hrow * 2 + 1] + bv1;
                if (mode == 0) {
                    v0 = gelu_exact(v0);
                    v1 = gelu_exact(v1);
                } else {
                    v0 += resid[ob];
                    v1 += resid[ob + 1];
                }
                if (mode == 2) {
                    outf[ob]     = v0;
                    outf[ob + 1] = v1;
                } else {
                    __half h0, l0, h1, l1;
                    split_f16(v0, h0, l0);
                    split_f16(v1, h1, l1);
                    __half2 ph; ph.x = h0; ph.y = h1;
                    __half2 pl; pl.x = l0; pl.y = l1;
                    *(__half2*)(Ohi + ob) = ph;
                    *(__half2*)(Olo + ob) = pl;
                }
            }
        }
    }
}

// ---------------------------------------------------------------------------
// Host driver
// ---------------------------------------------------------------------------
extern "C" void kernel_launch(void* const* d_in, const int* in_sizes, int n_in,
                              void* d_out, int out_size)
{
    const float* x        = (const float*)d_in[0];
    const float* bn_gamma = (const float*)d_in[1];
    const float* bn_beta  = (const float*)d_in[2];
    const float* selw1[3]; const float* selb1[3]; const float* selw2[3]; const float* selb2[3];
    const float* linw1[3]; const float* linb1[3]; const float* linw2[3]; const float* linb2[3];
    for (int s = 0; s < 3; s++) {
        int o = 3 + s * 8;
        selw1[s] = (const float*)d_in[o + 0];
        selb1[s] = (const float*)d_in[o + 1];
        selw2[s] = (const float*)d_in[o + 2];
        selb2[s] = (const float*)d_in[o + 3];
        linw1[s] = (const float*)d_in[o + 4];
        linb1[s] = (const float*)d_in[o + 5];
        linw2[s] = (const float*)d_in[o + 6];
        linb2[s] = (const float*)d_in[o + 7];
    }
    float* out = (float*)d_out;

    float* scr = nullptr;
    cudaGetSymbolAddress((void**)&scr, g_scratch);
    __half* hi = nullptr;
    cudaGetSymbolAddress((void**)&hi, g_hi);
    __half* lo = nullptr;
    cudaGetSymbolAddress((void**)&lo, g_lo);

    cudaFuncSetAttribute(gemm2_mma_kernel, cudaFuncAttributeMaxDynamicSharedMemorySize, GEMM_SMEM);

    float* mu    = scr + OFF_MU;
    float* rstd  = scr + OFF_RSTD;
    float* avg[3] = { scr + OFF_AVG0, scr + OFF_AVG1, scr + OFF_AVG2 };
    float* mx[3]  = { scr + OFF_MX0,  scr + OFF_MX1,  scr + OFF_MX2  };
    float* mixf1  = scr + OFF_MIXF1;
    float* mixf2  = scr + OFF_MIXF2;
    float* stats  = scr + OFF_STATS;
    float* wsel   = scr + OFF_W;

    // ---- all weight transposes (fp16, single plane)
    WJobs wj;
    const float* Wsrc[6] = { linw1[0], linw2[0], linw1[1], linw2[1], linw1[2], linw2[2] };
    const size_t Woff[6] = { BO_WT0A, BO_WT0B, BO_WT1A, BO_WT1B, BO_WT2A, BO_WT2B };
    const int    Wk[6]   = { 256, 256, 512, 512, 1024, 1024 };
    const int    Wn[6]   = { 256, 512, 512, 1024, 1024, 2048 };
    int pre = 0;
    for (int i = 0; i < 6; i++) {
        wj.W[i] = Wsrc[i]; wj.off[i] = Woff[i]; wj.K[i] = Wk[i]; wj.N[i] = Wn[i];
        wj.prefix[i] = pre;
        pre += (Wn[i] / 32) * (Wk[i] / 32);
    }
    wj.prefix[6] = pre;
    wsplit_all_kernel<<<pre, dim3(32, 8)>>>(wj, hi);

    // ---- BN stats, fused BN-apply + pooling + pfs stats
    bn_stats_kernel<<<FS / 256, 256>>>(x, mu, rstd);
    bn_pool_stats_kernel<<<MROWS, 256>>>(x, bn_gamma, bn_beta, mu, rstd, out,
                                         avg[0], mx[0], avg[1], mx[1], avg[2], mx[2],
                                         stats);

    // ---- all selectors
    SelParams sp;
    for (int s = 0; s < 3; s++) {
        sp.w1[s] = selw1[s]; sp.b1[s] = selb1[s]; sp.w2[s] = selw2[s]; sp.b2[s] = selb2[s];
    }
    selector_all_kernel<<<dim3(BB, 3), 256>>>(stats, sp, wsel);

    // ---- mixes + chained 2-term fp16 tensor-core GEMMs
    mix_split_kernel<<<(unsigned)(UU / 256), 256>>>(avg[0], mx[0], wsel + 0,
                                                    nullptr, hi + BO_MIX0, lo + BO_MIX0, 256);
    gemm2_mma_kernel<<<dim3(2, 64), 256, GEMM_SMEM>>>(
        hi + BO_MIX0, lo + BO_MIX0, hi + BO_WT0A,
        linb1[0], nullptr, nullptr, hi + BO_H0, lo + BO_H0, MROWS, 256, 256, 0);

    mix_split_kernel<<<(unsigned)(2 * UU / 256), 256>>>(avg[1], mx[1], wsel + 64,
                                                        mixf1, nullptr, nullptr, 512);
    gemm2_mma_kernel<<<dim3(4, 64), 256, GEMM_SMEM>>>(
        hi + BO_H0, lo + BO_H0, hi + BO_WT0B,
        linb2[0], mixf1, nullptr, hi + BO_S1, lo + BO_S1, MROWS, 512, 256, 1);

    mix_split_kernel<<<(unsigned)(4 * UU / 256), 256>>>(avg[2], mx[2], wsel + 128,
                                                        mixf2, nullptr, nullptr, 1024);
    gemm2_mma_kernel<<<dim3(4, 64), 256, GEMM_SMEM>>>(
        hi + BO_S1, lo + BO_S1, hi + BO_WT1A,
        linb1[1], nullptr, nullptr, hi + BO_H1, lo + BO_H1, MROWS, 512, 512, 0);
    gemm2_mma_kernel<<<dim3(8, 64), 256, GEMM_SMEM>>>(
        hi + BO_H1, lo + BO_H1, hi + BO_WT1B,
        linb2[1], mixf2, nullptr, hi + BO_S2, lo + BO_S2, MROWS, 1024, 512, 1);
    gemm2_mma_kernel<<<dim3(8, 64), 256, GEMM_SMEM>>>(
        hi + BO_S2, lo + BO_S2, hi + BO_WT2A,
        linb1[2], nullptr, nullptr, hi + BO_H2, lo + BO_H2, MROWS, 1024, 1024, 0);
    gemm2_mma_kernel<<<dim3(16, 64), 256, GEMM_SMEM>>>(
        hi + BO_H2, lo + BO_H2, hi + BO_WT2B,
        linb2[2], out, out, nullptr, nullptr, MROWS, 2048, 1024, 2);
}

// round 10
// speedup vs baseline: 1.2183x; 1.2183x over previous
#include <cuda_runtime.h>
#include <cuda_bf16.h>
#include <math.h>

typedef unsigned int       u32;
typedef unsigned long long u64;

// ---------------------------------------------------------------------------
// Problem constants
// ---------------------------------------------------------------------------
#define BB 64
#define FF 128
#define SS 2048
#define FS (FF * SS)          // 262144
#define MROWS (BB * FF)       // 8192
#define UU ((size_t)MROWS * 256)

// ---------------------------------------------------------------------------
// Baseline-PTX helpers
// ---------------------------------------------------------------------------
__device__ __forceinline__ u32 smem_to_u32(const void* p) {
    u32 a;
    asm("{ .reg .u64 t; cvta.to.shared.u64 t, %1; cvt.u32.u64 %0, t; }" : "=r"(a) : "l"(p));
    return a;
}
__device__ __forceinline__ void cp_async16(u32 dst, const void* src) {
    asm volatile("cp.async.cg.shared.global [%0], [%1], 16;" :: "r"(dst), "l"(src) : "memory");
}
#define CP_COMMIT() asm volatile("cp.async.commit_group;" ::: "memory")
#define CP_WAIT(n)  asm volatile("cp.async.wait_group %0;" :: "n"(n) : "memory")

__device__ __forceinline__ void ldsm_x4(u32* r, u32 addr) {
    asm volatile("ldmatrix.sync.aligned.m8n8.x4.shared.b16 {%0,%1,%2,%3}, [%4];"
                 : "=r"(r[0]), "=r"(r[1]), "=r"(r[2]), "=r"(r[3]) : "r"(addr));
}
__device__ __forceinline__ void mma_bf16(float* c, const u32* a, const u32* b) {
    asm volatile("mma.sync.aligned.m16n8k16.row.col.f32.bf16.bf16.f32 "
                 "{%0,%1,%2,%3}, {%4,%5,%6,%7}, {%8,%9}, {%0,%1,%2,%3};"
                 : "+f"(c[0]), "+f"(c[1]), "+f"(c[2]), "+f"(c[3])
                 : "r"(a[0]), "r"(a[1]), "r"(a[2]), "r"(a[3]), "r"(b[0]), "r"(b[1]));
}
#define SWZ(b) ((b) ^ (((b) >> 3) & 0x70))

// ---------------------------------------------------------------------------
// Static scratch arenas
// ---------------------------------------------------------------------------
#define OFF_MU     ((size_t)0)
#define OFF_RSTD   (OFF_MU + FS)
#define OFF_AVG0   (OFF_RSTD + FS)
#define OFF_MX0    (OFF_AVG0 + UU)
#define OFF_AVG1   (OFF_MX0 + UU)
#define OFF_MX1    (OFF_AVG1 + 2 * UU)
#define OFF_AVG2   (OFF_MX1 + 2 * UU)
#define OFF_MX2    (OFF_AVG2 + 4 * UU)
#define OFF_STATS  (OFF_MX2 + 4 * UU)
#define OFF_W      (OFF_STATS + (size_t)3 * 64 * 384)
#define SCRATCH_TOTAL (OFF_W + 3 * 64)
__device__ float g_scratch[SCRATCH_TOTAL];

// bf16 split arenas
#define BO_S1    ((size_t)0)                   // 8192 x 512
#define BO_S2    (BO_S1 + 2 * UU)              // 8192 x 1024
#define BO_H0    (BO_S2 + 4 * UU)              // 8192 x 256
#define BO_H1    (BO_H0 + UU)                  // 8192 x 512
#define BO_H2    (BO_H1 + 2 * UU)              // 8192 x 1024
#define BO_WT    (BO_H2 + 4 * UU)
#define BO_WT0A  (BO_WT)
#define BO_WT0B  (BO_WT0A + 256 * 256)
#define BO_WT1A  (BO_WT0B + 512 * 256)
#define BO_WT1B  (BO_WT1A + 512 * 512)
#define BO_WT2A  (BO_WT1B + 1024 * 512)
#define BO_WT2B  (BO_WT2A + 1024 * 1024)
#define BF_TOTAL (BO_WT2B + (size_t)2048 * 1024)
__device__ __nv_bfloat16 g_hi[BF_TOTAL];
__device__ __nv_bfloat16 g_lo[BF_TOTAL];

__device__ __forceinline__ void split_bf16(float v, __nv_bfloat16& h, __nv_bfloat16& l) {
    h = __float2bfloat16(v);
    l = __float2bfloat16(v - __bfloat162float(h));
}
__device__ __forceinline__ float gelu_exact(float v) {
    return 0.5f * v * (1.0f + erff(v * 0.70710678118654752f));
}

// ---------------------------------------------------------------------------
// 1) Fused pre-pass: bn_stats (blocks 0..1023) + weight transpose/split (rest)
// ---------------------------------------------------------------------------
struct WJobs {
    const float* W[6];
    size_t off[6];
    int K[6], N[6];
    int prefix[7];
};
__global__ __launch_bounds__(256)
void fused_pre_kernel(const float* __restrict__ x,
                      float* __restrict__ mu, float* __restrict__ rstd,
                      WJobs jobs, __nv_bfloat16* __restrict__ hib,
                      __nv_bfloat16* __restrict__ lob)
{
    if (blockIdx.x < 1024) {
        int j = blockIdx.x * 256 + threadIdx.x;
        float s = 0.f, ss = 0.f;
#pragma unroll 8
        for (int b = 0; b < BB; b++) {
            float v = x[(size_t)b * FS + j];
            s += v; ss += v * v;
        }
        float m   = s * (1.f / BB);
        float var = ss * (1.f / BB) - m * m;
        mu[j]   = m;
        rstd[j] = rsqrtf(var + 1e-5f);
        return;
    }
    __shared__ float tile[32][33];
    int bid = blockIdx.x - 1024;
    int j = 0;
#pragma unroll
    for (int i = 1; i < 6; i++)
        if (bid >= jobs.prefix[i]) j = i;
    int local = bid - jobs.prefix[j];
    int K = jobs.K[j], N = jobs.N[j];
    const float* W = jobs.W[j];
    __nv_bfloat16* Th = hib + jobs.off[j];
    __nv_bfloat16* Tl = lob + jobs.off[j];
    int tiles_x = N >> 5;
    int n0 = (local % tiles_x) << 5, k0 = (local / tiles_x) << 5;
    int tx = threadIdx.x & 31, ty = threadIdx.x >> 5;
#pragma unroll
    for (int i = 0; i < 32; i += 8)
        tile[ty + i][tx] = W[(size_t)(k0 + ty + i) * N + n0 + tx];
    __syncthreads();
#pragma unroll
    for (int i = 0; i < 32; i += 8) {
        float v = tile[tx][ty + i];
        __nv_bfloat16 h, l;
        split_bf16(v, h, l);
        size_t o = (size_t)(n0 + ty + i) * K + k0 + tx;
        Th[o] = h; Tl[o] = l;
    }
}

// ---------------------------------------------------------------------------
// 2) Fused BN apply + multi-scale pooling + pfs statistics.
// ---------------------------------------------------------------------------
__global__ __launch_bounds__(256)
void bn_pool_stats_kernel(const float* __restrict__ x,
                          const float* __restrict__ gamma,
                          const float* __restrict__ beta,
                          const float* __restrict__ mu,
                          const float* __restrict__ rstd,
                          float* __restrict__ xn,
                          float* __restrict__ avg0, float* __restrict__ mx0,
                          float* __restrict__ avg1, float* __restrict__ mx1,
                          float* __restrict__ avg2, float* __restrict__ mx2,
                          float* __restrict__ stats)
{
    const int bf = blockIdx.x;
    const int b  = bf >> 7;
    const int f  = bf & (FF - 1);
    const int t  = threadIdx.x;
    const size_t base = ((size_t)bf << 11) + (t << 3);
    const int j0 = (f << 11) + (t << 3);

    float4 xa = *(const float4*)(x + base);
    float4 xb = *(const float4*)(x + base + 4);
    float4 ma = *(const float4*)(mu + j0);
    float4 mb = *(const float4*)(mu + j0 + 4);
    float4 ra = *(const float4*)(rstd + j0);
    float4 rb = *(const float4*)(rstd + j0 + 4);
    float4 ga = *(const float4*)(gamma + j0);
    float4 gb = *(const float4*)(gamma + j0 + 4);
    float4 ba = *(const float4*)(beta + j0);
    float4 bb = *(const float4*)(beta + j0 + 4);

    float v[8];
    v[0] = (xa.x - ma.x) * ra.x * ga.x + ba.x;
    v[1] = (xa.y - ma.y) * ra.y * ga.y + ba.y;
    v[2] = (xa.z - ma.z) * ra.z * ga.z + ba.z;
    v[3] = (xa.w - ma.w) * ra.w * ga.w + ba.w;
    v[4] = (xb.x - mb.x) * rb.x * gb.x + bb.x;
    v[5] = (xb.y - mb.y) * rb.y * gb.y + bb.y;
    v[6] = (xb.z - mb.z) * rb.z * gb.z + bb.z;
    v[7] = (xb.w - mb.w) * rb.w * gb.w + bb.w;

    *(float4*)(xn + base)     = make_float4(v[0], v[1], v[2], v[3]);
    *(float4*)(xn + base + 4) = make_float4(v[4], v[5], v[6], v[7]);

    float a2[4], m2[4];
#pragma unroll
    for (int i = 0; i < 4; i++) {
        a2[i] = (v[2 * i] + v[2 * i + 1]) * 0.5f;
        m2[i] = fmaxf(v[2 * i], v[2 * i + 1]);
    }
    size_t b2 = ((size_t)bf << 10) + (t << 2);
#pragma unroll
    for (int i = 0; i < 4; i++) { avg2[b2 + i] = a2[i]; mx2[b2 + i] = m2[i]; }

    float a1[2], m1[2];
    a1[0] = (a2[0] + a2[1]) * 0.5f;  m1[0] = fmaxf(m2[0], m2[1]);
    a1[1] = (a2[2] + a2[3]) * 0.5f;  m1[1] = fmaxf(m2[2], m2[3]);
    size_t b1 = ((size_t)bf << 9) + (t << 1);
    avg1[b1] = a1[0]; mx1[b1] = m1[0];
    avg1[b1 + 1] = a1[1]; mx1[b1 + 1] = m1[1];

    float a0 = (a1[0] + a1[1]) * 0.5f;
    float m0 = fmaxf(m1[0], m1[1]);
    size_t b0 = ((size_t)bf << 8) + t;
    avg0[b0] = a0; mx0[b0] = m0;

    float s[3] = {0.f, 0.f, 0.f}, q[3] = {0.f, 0.f, 0.f}, mm[3] = {-1e30f, -1e30f, -1e30f};
    {
        float p = 0.5f * (a0 + m0);
        s[0] = p; q[0] = p * p; mm[0] = p;
    }
#pragma unroll
    for (int i = 0; i < 2; i++) {
        float p = 0.5f * (a1[i] + m1[i]);
        s[1] += p; q[1] += p * p; mm[1] = fmaxf(mm[1], p);
    }
#pragma unroll
    for (int i = 0; i < 4; i++) {
        float p = 0.5f * (a2[i] + m2[i]);
        s[2] += p; q[2] += p * p; mm[2] = fmaxf(mm[2], p);
    }

    const int lane = t & 31, warp = t >> 5;
#pragma unroll
    for (int off = 16; off > 0; off >>= 1) {
#pragma unroll
        for (int k = 0; k < 3; k++) {
            s[k]  += __shfl_down_sync(0xFFFFFFFFu, s[k], off);
            q[k]  += __shfl_down_sync(0xFFFFFFFFu, q[k], off);
            mm[k]  = fmaxf(mm[k], __shfl_down_sync(0xFFFFFFFFu, mm[k], off));
        }
    }
    __shared__ float red[8][9];
    if (lane == 0) {
#pragma unroll
        for (int k = 0; k < 3; k++) {
            red[warp][k] = s[k]; red[warp][3 + k] = q[k]; red[warp][6 + k] = mm[k];
        }
    }
    __syncthreads();
    if (t == 0) {
        const int Lsc[3] = {256, 512, 1024};
#pragma unroll
        for (int k = 0; k < 3; k++) {
            float S = 0.f, Q = 0.f, M = -1e30f;
#pragma unroll
            for (int w = 0; w < 8; w++) {
                S += red[w][k]; Q += red[w][3 + k]; M = fmaxf(M, red[w][6 + k]);
            }
            float L = (float)Lsc[k];
            float mean = S / L;
            float var  = (Q - S * mean) / (L - 1.f);
            float* st = stats + (size_t)k * 64 * 384 + b * 384;
            st[f]       = mean;
            st[128 + f] = sqrtf(fmaxf(var, 0.f));
            st[256 + f] = M;
        }
    }
}

// ---------------------------------------------------------------------------
// 3) Selector MLPs with smem-cached W1: grid (16,3), 4 batches per block.
// ---------------------------------------------------------------------------
struct SelParams {
    const float* w1[3]; const float* b1[3]; const float* w2[3]; const float* b2[3];
};
#define SEL_SMEM (384 * 64 * 4)
__global__ __launch_bounds__(256)
void selector_all_kernel(const float* __restrict__ stats, SelParams sp,
                         float* __restrict__ wout)
{
    extern __shared__ float w1s[];   // 384*64
    int s = blockIdx.y, bx = blockIdx.x;
    int tid = threadIdx.x;
    int p = tid >> 6, j = tid & 63;
    const float4* w1v = (const float4*)sp.w1[s];
    for (int i = tid; i < 384 * 64 / 4; i += 256)
        ((float4*)w1s)[i] = w1v[i];
    __shared__ float st[384];
    __shared__ float part[4][64];
    __shared__ float sh[64];
    for (int bb = 0; bb < 4; bb++) {
        int b = bx * 4 + bb;
        const float* sg = stats + (size_t)s * 64 * 384 + b * 384;
        __syncthreads();
        for (int i = tid; i < 384; i += 256) st[i] = sg[i];
        __syncthreads();
        float acc = 0.f;
#pragma unroll 8
        for (int i = p; i < 384; i += 4) acc += st[i] * w1s[i * 64 + j];
        part[p][j] = acc;
        __syncthreads();
        if (tid < 64) {
            float h = part[0][tid] + part[1][tid] + part[2][tid] + part[3][tid] + sp.b1[s][tid];
            sh[tid] = fmaxf(h, 0.f) * sp.w2[s][tid];
        }
        __syncthreads();
        if (tid < 32) {
            float v = sh[tid] + sh[tid + 32];
#pragma unroll
            for (int off = 16; off > 0; off >>= 1)
                v += __shfl_down_sync(0xFFFFFFFFu, v, off);
            if (tid == 0)
                wout[s * 64 + b] = 1.f / (1.f + expf(-(v + sp.b2[s][0])));
        }
    }
}

// ---------------------------------------------------------------------------
// 4) mma.sync bf16 3-term split GEMM, 3-stage pipeline.
//    amix=1: A built in-kernel from fp32 avg/mx + per-batch weight (scale 0).
//    mode 0: v = gelu(acc + bias)                         -> split bf16
//    mode 1: v = w*avg+(1-w)*mx + acc + bias (inline mix) -> split bf16
//    mode 2: v = outf + acc + bias                        -> fp32 (in-place)
// ---------------------------------------------------------------------------
#define TILE_BYTES 16384
#define STAGE_BYTES (4 * TILE_BYTES)
#define GEMM_SMEM (3 * STAGE_BYTES)

__global__ __launch_bounds__(256, 1)
void gemm3_mma_kernel(const __nv_bfloat16* __restrict__ Ahi, const __nv_bfloat16* __restrict__ Alo,
                      const __nv_bfloat16* __restrict__ Bhi, const __nv_bfloat16* __restrict__ Blo,
                      const float* __restrict__ bias,
                      const float* __restrict__ avgp, const float* __restrict__ mxp,
                      const float* __restrict__ wselp,
                      float* __restrict__ outf,
                      __nv_bfloat16* __restrict__ Ohi, __nv_bfloat16* __restrict__ Olo,
                      int M, int N, int K, int mode, int amix)
{
    extern __shared__ char smem[];
    const u32 sb = smem_to_u32(smem);
    const int tid = threadIdx.x;
    const int wid = tid >> 5, lane = tid & 31;
    const int m0 = blockIdx.y * 128, n0 = blockIdx.x * 128;
    const int wm = (wid & 1) * 64;
    const int wn = (wid >> 1) * 32;
    const float wmix = (amix || mode == 1) ? __ldg(wselp + (m0 >> 7)) : 0.f;

    float acc[4][4][4];
#pragma unroll
    for (int i = 0; i < 4; i++)
#pragma unroll
        for (int j = 0; j < 4; j++)
#pragma unroll
            for (int r = 0; r < 4; r++) acc[i][j][r] = 0.f;

    const int ntile = K >> 6;

#define ISSUE_B(T) do {                                                        \
        const int k0_ = (T) << 6;                                              \
        const u32 stage_ = ((T) % 3) * STAGE_BYTES;                            \
        _Pragma("unroll")                                                      \
        for (int rep = 0; rep < 4; rep++) {                                    \
            int idx = tid + rep * 256;                                         \
            int r = idx >> 3, c = idx & 7;                                     \
            u32 so = SWZ((u32)(r * 128 + c * 16));                             \
            size_t gb = (size_t)(n0 + r) * K + k0_ + c * 8;                    \
            cp_async16(sb + stage_ + 2 * TILE_BYTES + so, Bhi + gb);           \
            cp_async16(sb + stage_ + 3 * TILE_BYTES + so, Blo + gb);           \
        }                                                                      \
    } while (0)

#define ISSUE_A(T) do {                                                        \
        const int k0_ = (T) << 6;                                              \
        const u32 stage_ = ((T) % 3) * STAGE_BYTES;                            \
        _Pragma("unroll")                                                      \
        for (int rep = 0; rep < 4; rep++) {                                    \
            int idx = tid + rep * 256;                                         \
            int r = idx >> 3, c = idx & 7;                                     \
            u32 so = SWZ((u32)(r * 128 + c * 16));                             \
            size_t ga = (size_t)(m0 + r) * K + k0_ + c * 8;                    \
            cp_async16(sb + stage_ + 0 * TILE_BYTES + so, Ahi + ga);           \
            cp_async16(sb + stage_ + 1 * TILE_BYTES + so, Alo + ga);           \
        }                                                                      \
    } while (0)

#define FILL_A(T) do {                                                         \
        const int k0_ = (T) << 6;                                              \
        const u32 stage_ = ((T) % 3) * STAGE_BYTES;                            \
        _Pragma("unroll")                                                      \
        for (int rep = 0; rep < 4; rep++) {                                    \
            int idx = tid + rep * 256;                                         \
            int r = idx >> 3, c = idx & 7;                                     \
            u32 so = SWZ((u32)(r * 128 + c * 16));                             \
            const float* pa = avgp + (size_t)(m0 + r) * K + k0_ + c * 8;       \
            const float* pm = mxp  + (size_t)(m0 + r) * K + k0_ + c * 8;       \
            float4 a0 = *(const float4*)pa, a1 = *(const float4*)(pa + 4);     \
            float4 x0 = *(const float4*)pm, x1 = *(const float4*)(pm + 4);     \
            float vv[8];                                                       \
            vv[0] = wmix * a0.x + (1.f - wmix) * x0.x;                         \
            vv[1] = wmix * a0.y + (1.f - wmix) * x0.y;                         \
            vv[2] = wmix * a0.z + (1.f - wmix) * x0.z;                         \
            vv[3] = wmix * a0.w + (1.f - wmix) * x0.w;                         \
            vv[4] = wmix * a1.x + (1.f - wmix) * x1.x;                         \
            vv[5] = wmix * a1.y + (1.f - wmix) * x1.y;                         \
            vv[6] = wmix * a1.z + (1.f - wmix) * x1.z;                         \
            vv[7] = wmix * a1.w + (1.f - wmix) * x1.w;                         \
            __nv_bfloat16 hb[8], lb[8];                                        \
            _Pragma("unroll")                                                  \
            for (int e = 0; e < 8; e++) split_bf16(vv[e], hb[e], lb[e]);       \
            *(uint4*)(smem + stage_ + 0 * TILE_BYTES + so) = *(uint4*)hb;      \
            *(uint4*)(smem + stage_ + 1 * TILE_BYTES + so) = *(uint4*)lb;      \
        }                                                                      \
    } while (0)

    if (amix) {
        ISSUE_B(0); CP_COMMIT();
        if (ntile > 1) { ISSUE_B(1); CP_COMMIT(); }
    } else {
        ISSUE_A(0); ISSUE_B(0); CP_COMMIT();
        if (ntile > 1) { ISSUE_A(1); ISSUE_B(1); CP_COMMIT(); }
    }

    for (int t = 0; t < ntile; t++) {
        if (t + 1 < ntile) { CP_WAIT(1); } else { CP_WAIT(0); }
        if (amix) FILL_A(t);
        __syncthreads();
        if (t + 2 < ntile) {
            if (amix) { ISSUE_B(t + 2); CP_COMMIT(); }
            else      { ISSUE_A(t + 2); ISSUE_B(t + 2); CP_COMMIT(); }
        }

        const u32 stage = (t % 3) * STAGE_BYTES;
        const u32 sAhi = sb + stage + 0 * TILE_BYTES;
        const u32 sAlo = sb + stage + 1 * TILE_BYTES;
        const u32 sBhi = sb + stage + 2 * TILE_BYTES;
        const u32 sBlo = sb + stage + 3 * TILE_BYTES;

#pragma unroll
        for (int ks = 0; ks < 4; ks++) {
            u32 ah[4][4], al[4][4], bh[4][2], bl[4][2];
#pragma unroll
            for (int mb = 0; mb < 4; mb++) {
                int row = wm + mb * 16 + (lane & 15);
                u32 so = SWZ((u32)(row * 128 + ks * 32 + (lane >> 4) * 16));
                ldsm_x4(ah[mb], sAhi + so);
                ldsm_x4(al[mb], sAlo + so);
            }
#pragma unroll
            for (int nb2 = 0; nb2 < 2; nb2++) {
                int row = wn + nb2 * 16 + ((lane >> 4) << 3) + (lane & 7);
                u32 so = SWZ((u32)(row * 128 + ks * 32 + ((lane >> 3) & 1) * 16));
                u32 rh[4], rl[4];
                ldsm_x4(rh, sBhi + so);
                ldsm_x4(rl, sBlo + so);
                bh[2 * nb2][0] = rh[0]; bh[2 * nb2][1] = rh[1];
                bh[2 * nb2 + 1][0] = rh[2]; bh[2 * nb2 + 1][1] = rh[3];
                bl[2 * nb2][0] = rl[0]; bl[2 * nb2][1] = rl[1];
                bl[2 * nb2 + 1][0] = rl[2]; bl[2 * nb2 + 1][1] = rl[3];
            }
#pragma unroll
            for (int mb = 0; mb < 4; mb++)
#pragma unroll
                for (int nb = 0; nb < 4; nb++) {
                    mma_bf16(acc[mb][nb], ah[mb], bh[nb]);
                    mma_bf16(acc[mb][nb], ah[mb], bl[nb]);
                    mma_bf16(acc[mb][nb], al[mb], bh[nb]);
                }
        }
    }
#undef ISSUE_A
#undef ISSUE_B
#undef FILL_A

    const int g   = lane >> 2;
    const int tig = lane & 3;
#pragma unroll
    for (int mb = 0; mb < 4; mb++) {
#pragma unroll
        for (int nb = 0; nb < 4; nb++) {
            int col = n0 + wn + nb * 8 + 2 * tig;
            float bv0 = __ldg(bias + col), bv1 = __ldg(bias + col + 1);
#pragma unroll
            for (int hrow = 0; hrow < 2; hrow++) {
                int row = m0 + wm + mb * 16 + g + hrow * 8;
                size_t ob = (size_t)row * N + col;
                float v0 = acc[mb][nb][hrow * 2 + 0] + bv0;
                float v1 = acc[mb][nb][hrow * 2 + 1] + bv1;
                if (mode == 0) {
                    v0 = gelu_exact(v0);
                    v1 = gelu_exact(v1);
                } else if (mode == 1) {
                    v0 += wmix * avgp[ob]     + (1.f - wmix) * mxp[ob];
                    v1 += wmix * avgp[ob + 1] + (1.f - wmix) * mxp[ob + 1];
                } else {
                    v0 += outf[ob];
                    v1 += outf[ob + 1];
                }
                if (mode == 2) {
                    outf[ob]     = v0;
                    outf[ob + 1] = v1;
                } else {
                    __nv_bfloat16 h0, l0, h1, l1;
                    split_bf16(v0, h0, l0);
                    split_bf16(v1, h1, l1);
                    __nv_bfloat162 ph; ph.x = h0; ph.y = h1;
                    __nv_bfloat162 pl; pl.x = l0; pl.y = l1;
                    *(__nv_bfloat162*)(Ohi + ob) = ph;
                    *(__nv_bfloat162*)(Olo + ob) = pl;
                }
            }
        }
    }
}

// ---------------------------------------------------------------------------
// Host driver
// ---------------------------------------------------------------------------
extern "C" void kernel_launch(void* const* d_in, const int* in_sizes, int n_in,
                              void* d_out, int out_size)
{
    const float* x        = (const float*)d_in[0];
    const float* bn_gamma = (const float*)d_in[1];
    const float* bn_beta  = (const float*)d_in[2];
    const float* selw1[3]; const float* selb1[3]; const float* selw2[3]; const float* selb2[3];
    const float* linw1[3]; const float* linb1[3]; const float* linw2[3]; const float* linb2[3];
    for (int s = 0; s < 3; s++) {
        int o = 3 + s * 8;
        selw1[s] = (const float*)d_in[o + 0];
        selb1[s] = (const float*)d_in[o + 1];
        selw2[s] = (const float*)d_in[o + 2];
        selb2[s] = (const float*)d_in[o + 3];
        linw1[s] = (const float*)d_in[o + 4];
        linb1[s] = (const float*)d_in[o + 5];
        linw2[s] = (const float*)d_in[o + 6];
        linb2[s] = (const float*)d_in[o + 7];
    }
    float* out = (float*)d_out;

    float* scr = nullptr;
    cudaGetSymbolAddress((void**)&scr, g_scratch);
    __nv_bfloat16* hi = nullptr;
    cudaGetSymbolAddress((void**)&hi, g_hi);
    __nv_bfloat16* lo = nullptr;
    cudaGetSymbolAddress((void**)&lo, g_lo);

    cudaFuncSetAttribute(gemm3_mma_kernel, cudaFuncAttributeMaxDynamicSharedMemorySize, GEMM_SMEM);
    cudaFuncSetAttribute(selector_all_kernel, cudaFuncAttributeMaxDynamicSharedMemorySize, SEL_SMEM);

    float* mu    = scr + OFF_MU;
    float* rstd  = scr + OFF_RSTD;
    float* avg[3] = { scr + OFF_AVG0, scr + OFF_AVG1, scr + OFF_AVG2 };
    float* mx[3]  = { scr + OFF_MX0,  scr + OFF_MX1,  scr + OFF_MX2  };
    float* stats  = scr + OFF_STATS;
    float* wsel   = scr + OFF_W;

    // ---- launch 1: bn_stats + all weight transposes/splits
    WJobs wj;
    const float* Wsrc[6] = { linw1[0], linw2[0], linw1[1], linw2[1], linw1[2], linw2[2] };
    const size_t Woff[6] = { BO_WT0A, BO_WT0B, BO_WT1A, BO_WT1B, BO_WT2A, BO_WT2B };
    const int    Wk[6]   = { 256, 256, 512, 512, 1024, 1024 };
    const int    Wn[6]   = { 256, 512, 512, 1024, 1024, 2048 };
    int pre = 0;
    for (int i = 0; i < 6; i++) {
        wj.W[i] = Wsrc[i]; wj.off[i] = Woff[i]; wj.K[i] = Wk[i]; wj.N[i] = Wn[i];
        wj.prefix[i] = pre;
        pre += (Wn[i] / 32) * (Wk[i] / 32);
    }
    wj.prefix[6] = pre;
    fused_pre_kernel<<<1024 + pre, 256>>>(x, mu, rstd, wj, hi, lo);

    // ---- launch 2: fused BN-apply + pooling + pfs stats
    bn_pool_stats_kernel<<<MROWS, 256>>>(x, bn_gamma, bn_beta, mu, rstd, out,
                                         avg[0], mx[0], avg[1], mx[1], avg[2], mx[2],
                                         stats);

    // ---- launch 3: all selectors (smem-cached W1)
    SelParams sp;
    for (int s = 0; s < 3; s++) {
        sp.w1[s] = selw1[s]; sp.b1[s] = selb1[s]; sp.w2[s] = selw2[s]; sp.b2[s] = selb2[s];
    }
    selector_all_kernel<<<dim3(16, 3), 256, SEL_SMEM>>>(stats, sp, wsel);

    // ---- launch 4 (profiled): gemm0 with in-kernel mix of scale 0
    gemm3_mma_kernel<<<dim3(2, 64), 256, GEMM_SMEM>>>(
        nullptr, nullptr, hi + BO_WT0A, lo + BO_WT0A,
        linb1[0], avg[0], mx[0], wsel + 0,
        nullptr, hi + BO_H0, lo + BO_H0, MROWS, 256, 256, 0, 1);

    // ---- gemm1: S1 = mix1 + H0 @ W2_0 + b (mix inline in epilogue)
    gemm3_mma_kernel<<<dim3(4, 64), 256, GEMM_SMEM>>>(
        hi + BO_H0, lo + BO_H0, hi + BO_WT0B, lo + BO_WT0B,
        linb2[0], avg[1], mx[1], wsel + 64,
        nullptr, hi + BO_S1, lo + BO_S1, MROWS, 512, 256, 1, 0);

    // ---- gemm2: H1 = gelu(S1 @ W1_1 + b)
    gemm3_mma_kernel<<<dim3(4, 64), 256, GEMM_SMEM>>>(
        hi + BO_S1, lo + BO_S1, hi + BO_WT1A, lo + BO_WT1A,
        linb1[1], nullptr, nullptr, nullptr,
        nullptr, hi + BO_H1, lo + BO_H1, MROWS, 512, 512, 0, 0);

    // ---- gemm3: S2 = mix2 + H1 @ W2_1 + b
    gemm3_mma_kernel<<<dim3(8, 64), 256, GEMM_SMEM>>>(
        hi + BO_H1, lo + BO_H1, hi + BO_WT1B, lo + BO_WT1B,
        linb2[1], avg[2], mx[2], wsel + 128,
        nullptr, hi + BO_S2, lo + BO_S2, MROWS, 1024, 512, 1, 0);

    // ---- gemm4: H2 = gelu(S2 @ W1_2 + b)
    gemm3_mma_kernel<<<dim3(8, 64), 256, GEMM_SMEM>>>(
        hi + BO_S2, lo + BO_S2, hi + BO_WT2A, lo + BO_WT2A,
        linb1[2], nullptr, nullptr, nullptr,
        nullptr, hi + BO_H2, lo + BO_H2, MROWS, 1024, 1024, 0, 0);

    // ---- gemm5: out += H2 @ W2_2 + b (fp32, in-place on xn)
    gemm3_mma_kernel<<<dim3(16, 64), 256, GEMM_SMEM>>>(
        hi + BO_H2, lo + BO_H2, hi + BO_WT2B, lo + BO_WT2B,
        linb2[2], nullptr, nullptr, nullptr,
        out, nullptr, nullptr, MROWS, 2048, 1024, 2, 0);
}

// round 12
// speedup vs baseline: 1.2224x; 1.0034x over previous
#include <cuda_runtime.h>
#include <cuda_bf16.h>
#include <math.h>

typedef unsigned int       u32;
typedef unsigned long long u64;

// ---------------------------------------------------------------------------
// Problem constants
// ---------------------------------------------------------------------------
#define BB 64
#define FF 128
#define SS 2048
#define FS (FF * SS)          // 262144
#define MROWS (BB * FF)       // 8192
#define UU ((size_t)MROWS * 256)

// ---------------------------------------------------------------------------
// Baseline-PTX helpers
// ---------------------------------------------------------------------------
__device__ __forceinline__ u32 smem_to_u32(const void* p) {
    u32 a;
    asm("{ .reg .u64 t; cvta.to.shared.u64 t, %1; cvt.u32.u64 %0, t; }" : "=r"(a) : "l"(p));
    return a;
}
__device__ __forceinline__ void cp_async16(u32 dst, const void* src) {
    asm volatile("cp.async.cg.shared.global [%0], [%1], 16;" :: "r"(dst), "l"(src) : "memory");
}
#define CP_COMMIT() asm volatile("cp.async.commit_group;" ::: "memory")
#define CP_WAIT(n)  asm volatile("cp.async.wait_group %0;" :: "n"(n) : "memory")

__device__ __forceinline__ void ldsm_x4(u32* r, u32 addr) {
    asm volatile("ldmatrix.sync.aligned.m8n8.x4.shared.b16 {%0,%1,%2,%3}, [%4];"
                 : "=r"(r[0]), "=r"(r[1]), "=r"(r[2]), "=r"(r[3]) : "r"(addr));
}
__device__ __forceinline__ void mma_bf16(float* c, const u32* a, const u32* b) {
    asm volatile("mma.sync.aligned.m16n8k16.row.col.f32.bf16.bf16.f32 "
                 "{%0,%1,%2,%3}, {%4,%5,%6,%7}, {%8,%9}, {%0,%1,%2,%3};"
                 : "+f"(c[0]), "+f"(c[1]), "+f"(c[2]), "+f"(c[3])
                 : "r"(a[0]), "r"(a[1]), "r"(a[2]), "r"(a[3]), "r"(b[0]), "r"(b[1]));
}
#define SWZ(b) ((b) ^ (((b) >> 3) & 0x70))

// ---------------------------------------------------------------------------
// Static scratch arenas
// ---------------------------------------------------------------------------
#define OFF_MU     ((size_t)0)
#define OFF_RSTD   (OFF_MU + FS)
#define OFF_AVG0   (OFF_RSTD + FS)
#define OFF_MX0    (OFF_AVG0 + UU)
#define OFF_AVG1   (OFF_MX0 + UU)
#define OFF_MX1    (OFF_AVG1 + 2 * UU)
#define OFF_AVG2   (OFF_MX1 + 2 * UU)
#define OFF_MX2    (OFF_AVG2 + 4 * UU)
#define OFF_STATS  (OFF_MX2 + 4 * UU)
#define OFF_W      (OFF_STATS + (size_t)3 * 64 * 384)
#define SCRATCH_TOTAL (OFF_W + 3 * 64)
__device__ float g_scratch[SCRATCH_TOTAL];

// bf16 split arenas
#define BO_S1    ((size_t)0)
#define BO_S2    (BO_S1 + 2 * UU)
#define BO_H0    (BO_S2 + 4 * UU)
#define BO_H1    (BO_H0 + UU)
#define BO_H2    (BO_H1 + 2 * UU)
#define BO_WT    (BO_H2 + 4 * UU)
#define BO_WT0A  (BO_WT)
#define BO_WT0B  (BO_WT0A + 256 * 256)
#define BO_WT1A  (BO_WT0B + 512 * 256)
#define BO_WT1B  (BO_WT1A + 512 * 512)
#define BO_WT2A  (BO_WT1B + 1024 * 512)
#define BO_WT2B  (BO_WT2A + 1024 * 1024)
#define BF_TOTAL (BO_WT2B + (size_t)2048 * 1024)
__device__ __nv_bfloat16 g_hi[BF_TOTAL];
__device__ __nv_bfloat16 g_lo[BF_TOTAL];

__device__ __forceinline__ void split_bf16(float v, __nv_bfloat16& h, __nv_bfloat16& l) {
    h = __float2bfloat16(v);
    l = __float2bfloat16(v - __bfloat162float(h));
}
__device__ __forceinline__ float gelu_exact(float v) {
    return 0.5f * v * (1.0f + erff(v * 0.70710678118654752f));
}

// ---------------------------------------------------------------------------
// 1) Fused pre-pass: bn_stats (blocks 0..1023) + weight transpose/split (rest)
// ---------------------------------------------------------------------------
struct WJobs {
    const float* W[6];
    size_t off[6];
    int K[6], N[6];
    int prefix[7];
};
__global__ __launch_bounds__(256)
void fused_pre_kernel(const float* __restrict__ x,
                      float* __restrict__ mu, float* __restrict__ rstd,
                      WJobs jobs, __nv_bfloat16* __restrict__ hib,
                      __nv_bfloat16* __restrict__ lob)
{
    if (blockIdx.x < 1024) {
        int j = blockIdx.x * 256 + threadIdx.x;
        float s = 0.f, ss = 0.f;
#pragma unroll 8
        for (int b = 0; b < BB; b++) {
            float v = x[(size_t)b * FS + j];
            s += v; ss += v * v;
        }
        float m   = s * (1.f / BB);
        float var = ss * (1.f / BB) - m * m;
        mu[j]   = m;
        rstd[j] = rsqrtf(var + 1e-5f);
        return;
    }
    __shared__ float tile[32][33];
    int bid = blockIdx.x - 1024;
    int j = 0;
#pragma unroll
    for (int i = 1; i < 6; i++)
        if (bid >= jobs.prefix[i]) j = i;
    int local = bid - jobs.prefix[j];
    int K = jobs.K[j], N = jobs.N[j];
    const float* W = jobs.W[j];
    __nv_bfloat16* Th = hib + jobs.off[j];
    __nv_bfloat16* Tl = lob + jobs.off[j];
    int tiles_x = N >> 5;
    int n0 = (local % tiles_x) << 5, k0 = (local / tiles_x) << 5;
    int tx = threadIdx.x & 31, ty = threadIdx.x >> 5;
#pragma unroll
    for (int i = 0; i < 32; i += 8)
        tile[ty + i][tx] = W[(size_t)(k0 + ty + i) * N + n0 + tx];
    __syncthreads();
#pragma unroll
    for (int i = 0; i < 32; i += 8) {
        float v = tile[tx][ty + i];
        __nv_bfloat16 h, l;
        split_bf16(v, h, l);
        size_t o = (size_t)(n0 + ty + i) * K + k0 + tx;
        Th[o] = h; Tl[o] = l;
    }
}

// ---------------------------------------------------------------------------
// 2) Fused BN apply + multi-scale pooling + pfs statistics.
// ---------------------------------------------------------------------------
__global__ __launch_bounds__(256)
void bn_pool_stats_kernel(const float* __restrict__ x,
                          const float* __restrict__ gamma,
                          const float* __restrict__ beta,
                          const float* __restrict__ mu,
                          const float* __restrict__ rstd,
                          float* __restrict__ xn,
                          float* __restrict__ avg0, float* __restrict__ mx0,
                          float* __restrict__ avg1, float* __restrict__ mx1,
                          float* __restrict__ avg2, float* __restrict__ mx2,
                          float* __restrict__ stats)
{
    const int bf = blockIdx.x;
    const int b  = bf >> 7;
    const int f  = bf & (FF - 1);
    const int t  = threadIdx.x;
    const size_t base = ((size_t)bf << 11) + (t << 3);
    const int j0 = (f << 11) + (t << 3);

    float4 xa = *(const float4*)(x + base);
    float4 xb = *(const float4*)(x + base + 4);
    float4 ma = *(const float4*)(mu + j0);
    float4 mb = *(const float4*)(mu + j0 + 4);
    float4 ra = *(const float4*)(rstd + j0);
    float4 rb = *(const float4*)(rstd + j0 + 4);
    float4 ga = *(const float4*)(gamma + j0);
    float4 gb = *(const float4*)(gamma + j0 + 4);
    float4 ba = *(const float4*)(beta + j0);
    float4 bb = *(const float4*)(beta + j0 + 4);

    float v[8];
    v[0] = (xa.x - ma.x) * ra.x * ga.x + ba.x;
    v[1] = (xa.y - ma.y) * ra.y * ga.y + ba.y;
    v[2] = (xa.z - ma.z) * ra.z * ga.z + ba.z;
    v[3] = (xa.w - ma.w) * ra.w * ga.w + ba.w;
    v[4] = (xb.x - mb.x) * rb.x * gb.x + bb.x;
    v[5] = (xb.y - mb.y) * rb.y * gb.y + bb.y;
    v[6] = (xb.z - mb.z) * rb.z * gb.z + bb.z;
    v[7] = (xb.w - mb.w) * rb.w * gb.w + bb.w;

    *(float4*)(xn + base)     = make_float4(v[0], v[1], v[2], v[3]);
    *(float4*)(xn + base + 4) = make_float4(v[4], v[5], v[6], v[7]);

    float a2[4], m2[4];
#pragma unroll
    for (int i = 0; i < 4; i++) {
        a2[i] = (v[2 * i] + v[2 * i + 1]) * 0.5f;
        m2[i] = fmaxf(v[2 * i], v[2 * i + 1]);
    }
    size_t b2 = ((size_t)bf << 10) + (t << 2);
#pragma unroll
    for (int i = 0; i < 4; i++) { avg2[b2 + i] = a2[i]; mx2[b2 + i] = m2[i]; }

    float a1[2], m1[2];
    a1[0] = (a2[0] + a2[1]) * 0.5f;  m1[0] = fmaxf(m2[0], m2[1]);
    a1[1] = (a2[2] + a2[3]) * 0.5f;  m1[1] = fmaxf(m2[2], m2[3]);
    size_t b1 = ((size_t)bf << 9) + (t << 1);
    avg1[b1] = a1[0]; mx1[b1] = m1[0];
    avg1[b1 + 1] = a1[1]; mx1[b1 + 1] = m1[1];

    float a0 = (a1[0] + a1[1]) * 0.5f;
    float m0 = fmaxf(m1[0], m1[1]);
    size_t b0 = ((size_t)bf << 8) + t;
    avg0[b0] = a0; mx0[b0] = m0;

    float s[3] = {0.f, 0.f, 0.f}, q[3] = {0.f, 0.f, 0.f}, mm[3] = {-1e30f, -1e30f, -1e30f};
    {
        float p = 0.5f * (a0 + m0);
        s[0] = p; q[0] = p * p; mm[0] = p;
    }
#pragma unroll
    for (int i = 0; i < 2; i++) {
        float p = 0.5f * (a1[i] + m1[i]);
        s[1] += p; q[1] += p * p; mm[1] = fmaxf(mm[1], p);
    }
#pragma unroll
    for (int i = 0; i < 4; i++) {
        float p = 0.5f * (a2[i] + m2[i]);
        s[2] += p; q[2] += p * p; mm[2] = fmaxf(mm[2], p);
    }

    const int lane = t & 31, warp = t >> 5;
#pragma unroll
    for (int off = 16; off > 0; off >>= 1) {
#pragma unroll
        for (int k = 0; k < 3; k++) {
            s[k]  += __shfl_down_sync(0xFFFFFFFFu, s[k], off);
            q[k]  += __shfl_down_sync(0xFFFFFFFFu, q[k], off);
            mm[k]  = fmaxf(mm[k], __shfl_down_sync(0xFFFFFFFFu, mm[k], off));
        }
    }
    __shared__ float red[8][9];
    if (lane == 0) {
#pragma unroll
        for (int k = 0; k < 3; k++) {
            red[warp][k] = s[k]; red[warp][3 + k] = q[k]; red[warp][6 + k] = mm[k];
        }
    }
    __syncthreads();
    if (t == 0) {
        const int Lsc[3] = {256, 512, 1024};
#pragma unroll
        for (int k = 0; k < 3; k++) {
            float S = 0.f, Q = 0.f, M = -1e30f;
#pragma unroll
            for (int w = 0; w < 8; w++) {
                S += red[w][k]; Q += red[w][3 + k]; M = fmaxf(M, red[w][6 + k]);
            }
            float L = (float)Lsc[k];
            float mean = S / L;
            float var  = (Q - S * mean) / (L - 1.f);
            float* st = stats + (size_t)k * 64 * 384 + b * 384;
            st[f]       = mean;
            st[128 + f] = sqrtf(fmaxf(var, 0.f));
            st[256 + f] = M;
        }
    }
}

// ---------------------------------------------------------------------------
// 3) Selector MLPs with smem-cached W1: grid (16,3), 4 batches per block.
// ---------------------------------------------------------------------------
struct SelParams {
    const float* w1[3]; const float* b1[3]; const float* w2[3]; const float* b2[3];
};
#define SEL_SMEM (384 * 64 * 4)
__global__ __launch_bounds__(256)
void selector_all_kernel(const float* __restrict__ stats, SelParams sp,
                         float* __restrict__ wout)
{
    extern __shared__ float w1s[];
    int s = blockIdx.y, bx = blockIdx.x;
    int tid = threadIdx.x;
    int p = tid >> 6, j = tid & 63;
    const float4* w1v = (const float4*)sp.w1[s];
    for (int i = tid; i < 384 * 64 / 4; i += 256)
        ((float4*)w1s)[i] = w1v[i];
    __shared__ float st[384];
    __shared__ float part[4][64];
    __shared__ float sh[64];
    for (int bb = 0; bb < 4; bb++) {
        int b = bx * 4 + bb;
        const float* sg = stats + (size_t)s * 64 * 384 + b * 384;
        __syncthreads();
        for (int i = tid; i < 384; i += 256) st[i] = sg[i];
        __syncthreads();
        float acc = 0.f;
#pragma unroll 8
        for (int i = p; i < 384; i += 4) acc += st[i] * w1s[i * 64 + j];
        part[p][j] = acc;
        __syncthreads();
        if (tid < 64) {
            float h = part[0][tid] + part[1][tid] + part[2][tid] + part[3][tid] + sp.b1[s][tid];
            sh[tid] = fmaxf(h, 0.f) * sp.w2[s][tid];
        }
        __syncthreads();
        if (tid < 32) {
            float v = sh[tid] + sh[tid + 32];
#pragma unroll
            for (int off = 16; off > 0; off >>= 1)
                v += __shfl_down_sync(0xFFFFFFFFu, v, off);
            if (tid == 0)
                wout[s * 64 + b] = 1.f / (1.f + expf(-(v + sp.b2[s][0])));
        }
    }
}

// ---------------------------------------------------------------------------
// 4) mma.sync bf16 3-term split GEMM — 512 threads, 16 warps (4M x 4N),
//    warp tile 32x32, CTA 128x128, K-chunk 64, 3-stage pipeline.
// ---------------------------------------------------------------------------
#define TILE_BYTES 16384
#define STAGE_BYTES (4 * TILE_BYTES)
#define GEMM_SMEM (3 * STAGE_BYTES)
#define GTH 512

__global__ __launch_bounds__(GTH, 1)
void gemm3_mma_kernel(const __nv_bfloat16* __restrict__ Ahi, const __nv_bfloat16* __restrict__ Alo,
                      const __nv_bfloat16* __restrict__ Bhi, const __nv_bfloat16* __restrict__ Blo,
                      const float* __restrict__ bias,
                      const float* __restrict__ avgp, const float* __restrict__ mxp,
                      const float* __restrict__ wselp,
                      float* __restrict__ outf,
                      __nv_bfloat16* __restrict__ Ohi, __nv_bfloat16* __restrict__ Olo,
                      int M, int N, int K, int mode, int amix)
{
    extern __shared__ char smem[];
    const u32 sb = smem_to_u32(smem);
    const int tid = threadIdx.x;
    const int wid = tid >> 5, lane = tid & 31;
    const int m0 = blockIdx.y * 128, n0 = blockIdx.x * 128;
    const int wm = (wid & 3) * 32;         // 4 M-warps x 32 rows
    const int wn = (wid >> 2) * 32;        // 4 N-warps x 32 cols
    const float wmix = (amix || mode == 1) ? __ldg(wselp + (m0 >> 7)) : 0.f;

    float acc[2][4][4];
#pragma unroll
    for (int i = 0; i < 2; i++)
#pragma unroll
        for (int j = 0; j < 4; j++)
#pragma unroll
            for (int r = 0; r < 4; r++) acc[i][j][r] = 0.f;

    const int ntile = K >> 6;

#define ISSUE_B(T) do {                                                        \
        const int k0_ = (T) << 6;                                              \
        const u32 stage_ = ((T) % 3) * STAGE_BYTES;                            \
        _Pragma("unroll")                                                      \
        for (int rep = 0; rep < 2; rep++) {                                    \
            int idx = tid + rep * GTH;                                         \
            int r = idx >> 3, c = idx & 7;                                     \
            u32 so = SWZ((u32)(r * 128 + c * 16));                             \
            size_t gb = (size_t)(n0 + r) * K + k0_ + c * 8;                    \
            cp_async16(sb + stage_ + 2 * TILE_BYTES + so, Bhi + gb);           \
            cp_async16(sb + stage_ + 3 * TILE_BYTES + so, Blo + gb);           \
        }                                                                      \
    } while (0)

#define ISSUE_A(T) do {                                                        \
        const int k0_ = (T) << 6;                                              \
        const u32 stage_ = ((T) % 3) * STAGE_BYTES;                            \
        _Pragma("unroll")                                                      \
        for (int rep = 0; rep < 2; rep++) {                                    \
            int idx = tid + rep * GTH;                                         \
            int r = idx >> 3, c = idx & 7;                                     \
            u32 so = SWZ((u32)(r * 128 + c * 16));                             \
            size_t ga = (size_t)(m0 + r) * K + k0_ + c * 8;                    \
            cp_async16(sb + stage_ + 0 * TILE_BYTES + so, Ahi + ga);           \
            cp_async16(sb + stage_ + 1 * TILE_BYTES + so, Alo + ga);           \
        }                                                                      \
    } while (0)

#define FILL_A(T) do {                                                         \
        const int k0_ = (T) << 6;                                              \
        const u32 stage_ = ((T) % 3) * STAGE_BYTES;                            \
        _Pragma("unroll")                                                      \
        for (int rep = 0; rep < 2; rep++) {                                    \
            int idx = tid + rep * GTH;                                         \
            int r = idx >> 3, c = idx & 7;                                     \
            u32 so = SWZ((u32)(r * 128 + c * 16));                             \
            const float* pa = avgp + (size_t)(m0 + r) * K + k0_ + c * 8;       \
            const float* pm = mxp  + (size_t)(m0 + r) * K + k0_ + c * 8;       \
            float4 a0 = *(const float4*)pa, a1 = *(const float4*)(pa + 4);     \
            float4 x0 = *(const float4*)pm, x1 = *(const float4*)(pm + 4);     \
            float vv[8];                                                       \
            vv[0] = wmix * a0.x + (1.f - wmix) * x0.x;                         \
            vv[1] = wmix * a0.y + (1.f - wmix) * x0.y;                         \
            vv[2] = wmix * a0.z + (1.f - wmix) * x0.z;                         \
            vv[3] = wmix * a0.w + (1.f - wmix) * x0.w;                         \
            vv[4] = wmix * a1.x + (1.f - wmix) * x1.x;                         \
            vv[5] = wmix * a1.y + (1.f - wmix) * x1.y;                         \
            vv[6] = wmix * a1.z + (1.f - wmix) * x1.z;                         \
            vv[7] = wmix * a1.w + (1.f - wmix) * x1.w;                         \
            __nv_bfloat16 hb[8], lb[8];                                        \
            _Pragma("unroll")                                                  \
            for (int e = 0; e < 8; e++) split_bf16(vv[e], hb[e], lb[e]);       \
            *(uint4*)(smem + stage_ + 0 * TILE_BYTES + so) = *(uint4*)hb;      \
            *(uint4*)(smem + stage_ + 1 * TILE_BYTES + so) = *(uint4*)lb;      \
        }                                                                      \
    } while (0)

    if (amix) {
        ISSUE_B(0); CP_COMMIT();
        if (ntile > 1) { ISSUE_B(1); CP_COMMIT(); }
    } else {
        ISSUE_A(0); ISSUE_B(0); CP_COMMIT();
        if (ntile > 1) { ISSUE_A(1); ISSUE_B(1); CP_COMMIT(); }
    }

    for (int t = 0; t < ntile; t++) {
        if (t + 1 < ntile) { CP_WAIT(1); } else { CP_WAIT(0); }
        if (amix) FILL_A(t);
        __syncthreads();
        if (t + 2 < ntile) {
            if (amix) { ISSUE_B(t + 2); CP_COMMIT(); }
            else      { ISSUE_A(t + 2); ISSUE_B(t + 2); CP_COMMIT(); }
        }

        const u32 stage = (t % 3) * STAGE_BYTES;
        const u32 sAhi = sb + stage + 0 * TILE_BYTES;
        const u32 sAlo = sb + stage + 1 * TILE_BYTES;
        const u32 sBhi = sb + stage + 2 * TILE_BYTES;
        const u32 sBlo = sb + stage + 3 * TILE_BYTES;

#pragma unroll
        for (int ks = 0; ks < 4; ks++) {
            u32 ah[2][4], al[2][4], bh[4][2], bl[4][2];
#pragma unroll
            for (int mb = 0; mb < 2; mb++) {
                int row = wm + mb * 16 + (lane & 15);
                u32 so = SWZ((u32)(row * 128 + ks * 32 + (lane >> 4) * 16));
                ldsm_x4(ah[mb], sAhi + so);
                ldsm_x4(al[mb], sAlo + so);
            }
#pragma unroll
            for (int nb2 = 0; nb2 < 2; nb2++) {
                int row = wn + nb2 * 16 + ((lane >> 4) << 3) + (lane & 7);
                u32 so = SWZ((u32)(row * 128 + ks * 32 + ((lane >> 3) & 1) * 16));
                u32 rh[4], rl[4];
                ldsm_x4(rh, sBhi + so);
                ldsm_x4(rl, sBlo + so);
                bh[2 * nb2][0] = rh[0]; bh[2 * nb2][1] = rh[1];
                bh[2 * nb2 + 1][0] = rh[2]; bh[2 * nb2 + 1][1] = rh[3];
                bl[2 * nb2][0] = rl[0]; bl[2 * nb2][1] = rl[1];
                bl[2 * nb2 + 1][0] = rl[2]; bl[2 * nb2 + 1][1] = rl[3];
            }
#pragma unroll
            for (int mb = 0; mb < 2; mb++)
#pragma unroll
                for (int nb = 0; nb < 4; nb++) {
                    mma_bf16(acc[mb][nb], ah[mb], bh[nb]);
                    mma_bf16(acc[mb][nb], ah[mb], bl[nb]);
                    mma_bf16(acc[mb][nb], al[mb], bh[nb]);
                }
        }
    }
#undef ISSUE_A
#undef ISSUE_B
#undef FILL_A

    const int g   = lane >> 2;
    const int tig = lane & 3;
#pragma unroll
    for (int mb = 0; mb < 2; mb++) {
#pragma unroll
        for (int nb = 0; nb < 4; nb++) {
            int col = n0 + wn + nb * 8 + 2 * tig;
            float bv0 = __ldg(bias + col), bv1 = __ldg(bias + col + 1);
#pragma unroll
            for (int hrow = 0; hrow < 2; hrow++) {
                int row = m0 + wm + mb * 16 + g + hrow * 8;
                size_t ob = (size_t)row * N + col;
                float v0 = acc[mb][nb][hrow * 2 + 0] + bv0;
                float v1 = acc[mb][nb][hrow * 2 + 1] + bv1;
                if (mode == 0) {
                    v0 = gelu_exact(v0);
                    v1 = gelu_exact(v1);
                } else if (mode == 1) {
                    v0 += wmix * avgp[ob]     + (1.f - wmix) * mxp[ob];
                    v1 += wmix * avgp[ob + 1] + (1.f - wmix) * mxp[ob + 1];
                } else {
                    v0 += outf[ob];
                    v1 += outf[ob + 1];
                }
                if (mode == 2) {
                    outf[ob]     = v0;
                    outf[ob + 1] = v1;
                } else {
                    __nv_bfloat16 h0, l0, h1, l1;
                    split_bf16(v0, h0, l0);
                    split_bf16(v1, h1, l1);
                    __nv_bfloat162 ph; ph.x = h0; ph.y = h1;
                    __nv_bfloat162 pl; pl.x = l0; pl.y = l1;
                    *(__nv_bfloat162*)(Ohi + ob) = ph;
                    *(__nv_bfloat162*)(Olo + ob) = pl;
                }
            }
        }
    }
}

// ---------------------------------------------------------------------------
// Host driver
// ---------------------------------------------------------------------------
extern "C" void kernel_launch(void* const* d_in, const int* in_sizes, int n_in,
                              void* d_out, int out_size)
{
    const float* x        = (const float*)d_in[0];
    const float* bn_gamma = (const float*)d_in[1];
    const float* bn_beta  = (const float*)d_in[2];
    const float* selw1[3]; const float* selb1[3]; const float* selw2[3]; const float* selb2[3];
    const float* linw1[3]; const float* linb1[3]; const float* linw2[3]; const float* linb2[3];
    for (int s = 0; s < 3; s++) {
        int o = 3 + s * 8;
        selw1[s] = (const float*)d_in[o + 0];
        selb1[s] = (const float*)d_in[o + 1];
        selw2[s] = (const float*)d_in[o + 2];
        selb2[s] = (const float*)d_in[o + 3];
        linw1[s] = (const float*)d_in[o + 4];
        linb1[s] = (const float*)d_in[o + 5];
        linw2[s] = (const float*)d_in[o + 6];
        linb2[s] = (const float*)d_in[o + 7];
    }
    float* out = (float*)d_out;

    float* scr = nullptr;
    cudaGetSymbolAddress((void**)&scr, g_scratch);
    __nv_bfloat16* hi = nullptr;
    cudaGetSymbolAddress((void**)&hi, g_hi);
    __nv_bfloat16* lo = nullptr;
    cudaGetSymbolAddress((void**)&lo, g_lo);

    cudaFuncSetAttribute(gemm3_mma_kernel, cudaFuncAttributeMaxDynamicSharedMemorySize, GEMM_SMEM);
    cudaFuncSetAttribute(selector_all_kernel, cudaFuncAttributeMaxDynamicSharedMemorySize, SEL_SMEM);

    float* mu    = scr + OFF_MU;
    float* rstd  = scr + OFF_RSTD;
    float* avg[3] = { scr + OFF_AVG0, scr + OFF_AVG1, scr + OFF_AVG2 };
    float* mx[3]  = { scr + OFF_MX0,  scr + OFF_MX1,  scr + OFF_MX2  };
    float* stats  = scr + OFF_STATS;
    float* wsel   = scr + OFF_W;

    // ---- launch 1: bn_stats + all weight transposes/splits
    WJobs wj;
    const float* Wsrc[6] = { linw1[0], linw2[0], linw1[1], linw2[1], linw1[2], linw2[2] };
    const size_t Woff[6] = { BO_WT0A, BO_WT0B, BO_WT1A, BO_WT1B, BO_WT2A, BO_WT2B };
    const int    Wk[6]   = { 256, 256, 512, 512, 1024, 1024 };
    const int    Wn[6]   = { 256, 512, 512, 1024, 1024, 2048 };
    int pre = 0;
    for (int i = 0; i < 6; i++) {
        wj.W[i] = Wsrc[i]; wj.off[i] = Woff[i]; wj.K[i] = Wk[i]; wj.N[i] = Wn[i];
        wj.prefix[i] = pre;
        pre += (Wn[i] / 32) * (Wk[i] / 32);
    }
    wj.prefix[6] = pre;
    fused_pre_kernel<<<1024 + pre, 256>>>(x, mu, rstd, wj, hi, lo);

    // ---- launch 2: fused BN-apply + pooling + pfs stats
    bn_pool_stats_kernel<<<MROWS, 256>>>(x, bn_gamma, bn_beta, mu, rstd, out,
                                         avg[0], mx[0], avg[1], mx[1], avg[2], mx[2],
                                         stats);

    // ---- launch 3: all selectors
    SelParams sp;
    for (int s = 0; s < 3; s++) {
        sp.w1[s] = selw1[s]; sp.b1[s] = selb1[s]; sp.w2[s] = selw2[s]; sp.b2[s] = selb2[s];
    }
    selector_all_kernel<<<dim3(16, 3), 256, SEL_SMEM>>>(stats, sp, wsel);

    // ---- launch 4 (profiled): gemm0 with in-kernel mix of scale 0
    gemm3_mma_kernel<<<dim3(2, 64), GTH, GEMM_SMEM>>>(
        nullptr, nullptr, hi + BO_WT0A, lo + BO_WT0A,
        linb1[0], avg[0], mx[0], wsel + 0,
        nullptr, hi + BO_H0, lo + BO_H0, MROWS, 256, 256, 0, 1);

    // ---- gemm1: S1 = mix1 + H0 @ W2_0 + b
    gemm3_mma_kernel<<<dim3(4, 64), GTH, GEMM_SMEM>>>(
        hi + BO_H0, lo + BO_H0, hi + BO_WT0B, lo + BO_WT0B,
        linb2[0], avg[1], mx[1], wsel + 64,
        nullptr, hi + BO_S1, lo + BO_S1, MROWS, 512, 256, 1, 0);

    // ---- gemm2: H1 = gelu(S1 @ W1_1 + b)
    gemm3_mma_kernel<<<dim3(4, 64), GTH, GEMM_SMEM>>>(
        hi + BO_S1, lo + BO_S1, hi + BO_WT1A, lo + BO_WT1A,
        linb1[1], nullptr, nullptr, nullptr,
        nullptr, hi + BO_H1, lo + BO_H1, MROWS, 512, 512, 0, 0);

    // ---- gemm3: S2 = mix2 + H1 @ W2_1 + b
    gemm3_mma_kernel<<<dim3(8, 64), GTH, GEMM_SMEM>>>(
        hi + BO_H1, lo + BO_H1, hi + BO_WT1B, lo + BO_WT1B,
        linb2[1], avg[2], mx[2], wsel + 128,
        nullptr, hi + BO_S2, lo + BO_S2, MROWS, 1024, 512, 1, 0);

    // ---- gemm4: H2 = gelu(S2 @ W1_2 + b)
    gemm3_mma_kernel<<<dim3(8, 64), GTH, GEMM_SMEM>>>(
        hi + BO_S2, lo + BO_S2, hi + BO_WT2A, lo + BO_WT2A,
        linb1[2], nullptr, nullptr, nullptr,
        nullptr, hi + BO_H2, lo + BO_H2, MROWS, 1024, 1024, 0, 0);

    // ---- gemm5: out += H2 @ W2_2 + b (fp32, in-place)
    gemm3_mma_kernel<<<dim3(16, 64), GTH, GEMM_SMEM>>>(
        hi + BO_H2, lo + BO_H2, hi + BO_WT2B, lo + BO_WT2B,
        linb2[2], nullptr, nullptr, nullptr,
        out, nullptr, nullptr, MROWS, 2048, 1024, 2, 0);
}